// round 14
// baseline (speedup 1.0000x reference)
#include <cuda_runtime.h>
#include <cuda_fp16.h>
#include <cstdint>
#include <cstddef>

#define DH __host__ __device__

DH constexpr double tcos_core(double x) {
    double x2 = x * x, t = 1.0, s = 1.0;
    for (int i = 1; i <= 12; i++) { t *= -x2 / (double)((2 * i - 1) * (2 * i)); s += t; }
    return s;
}
DH constexpr double dcosg(int f, int p, int N) {
    int m = ((2 * p + 1) * f) % (4 * N);
    double sg = 1.0;
    if (m > 2 * N) m = 4 * N - m;
    if (m > N) { sg = -1.0; m = 2 * N - m; }
    const double PI = 3.14159265358979323846264338327950288;
    return sg * tcos_core((double)m * PI / (2.0 * N));
}
DH constexpr double rsqrt2c() {
    double g = 0.7;
    for (int i = 0; i < 50; i++) g = 0.5 * (g + 0.5 / g);
    return g;
}
DH constexpr double fac1(int v) { return (v == 0) ? rsqrt2c() : 1.0; }
DH constexpr float codd(int w, int p) { return (float)(dcosg(2 * w + 1, p, 32) * fac1(2 * w + 1)); }
DH constexpr float ceo (int t, int q) { return (float)(dcosg(2 * t + 1, q, 16) * fac1(4 * t + 2)); }
DH constexpr float cee (int t, int q) { return (float)(dcosg(t,         q,  8) * fac1(4 * t)); }

// ---- vertical level-2 butterfly DCT (folds c_v), 32 rows stride 512 -> out[32] ----
template <int P, int W> struct OddW {
    static __device__ __forceinline__ void run(float dv, float (&a)[16]) {
        a[W] = fmaf(dv, codd(W, P), a[W]); OddW<P, W + 1>::run(dv, a);
    }
};
template <int P> struct OddW<P, 16> { static __device__ __forceinline__ void run(float, float (&)[16]) {} };
template <int P> struct OddIn {
    static __device__ __forceinline__ void run(const float (&d)[16], float (&a)[16]) {
        OddW<P, 0>::run(d[P], a); OddIn<P + 1>::run(d, a);
    }
};
template <> struct OddIn<16> { static __device__ __forceinline__ void run(const float (&)[16], float (&)[16]) {} };
template <int Q, int T> struct EvW {
    static __device__ __forceinline__ void run(float sv, float dv, float (&ae)[8], float (&ao)[8]) {
        ae[T] = fmaf(sv, cee(T, Q), ae[T]); ao[T] = fmaf(dv, ceo(T, Q), ao[T]);
        EvW<Q, T + 1>::run(sv, dv, ae, ao);
    }
};
template <int Q> struct EvW<Q, 8> { static __device__ __forceinline__ void run(float, float, float (&)[8], float (&)[8]) {} };
template <int Q> struct EvIn {
    static __device__ __forceinline__ void run(const float (&ss)[8], const float (&sd)[8], float (&ae)[8], float (&ao)[8]) {
        EvW<Q, 0>::run(ss[Q], sd[Q], ae, ao); EvIn<Q + 1>::run(ss, sd, ae, ao);
    }
};
template <> struct EvIn<8> { static __device__ __forceinline__ void run(const float (&)[8], const float (&)[8], float (&)[8], float (&)[8]) {} };

__device__ __forceinline__ void vdct32(const float* __restrict__ q, float (&out)[32]) {
    float s[16], d[16];
    #pragma unroll
    for (int P = 0; P < 16; P++) { float lo = q[P * 512], hi = q[(31 - P) * 512]; s[P] = lo + hi; d[P] = lo - hi; }
    float ao[16];
    #pragma unroll
    for (int w = 0; w < 16; w++) ao[w] = 0.f;
    OddIn<0>::run(d, ao);
    float ss[8], sd[8];
    #pragma unroll
    for (int q2 = 0; q2 < 8; q2++) { ss[q2] = s[q2] + s[15 - q2]; sd[q2] = s[q2] - s[15 - q2]; }
    float ae[8], ao2[8];
    #pragma unroll
    for (int t = 0; t < 8; t++) { ae[t] = 0.f; ao2[t] = 0.f; }
    EvIn<0>::run(ss, sd, ae, ao2);
    #pragma unroll
    for (int w = 0; w < 16; w++) out[2 * w + 1] = ao[w];
    #pragma unroll
    for (int t = 0; t < 8; t++) { out[4 * t] = ae[t]; out[4 * t + 2] = ao2[t]; }
}

__device__ __forceinline__ uint32_t smem_u32(const void* p) {
    uint32_t a;
    asm("{ .reg .u64 t; cvta.to.shared.u64 t, %1; cvt.u32.u64 %0, t; }" : "=r"(a) : "l"(p));
    return a;
}
__device__ __forceinline__ void ldmatrix_x4(uint32_t& r0, uint32_t& r1, uint32_t& r2, uint32_t& r3, uint32_t addr) {
    asm volatile("ldmatrix.sync.aligned.m8n8.x4.shared.b16 {%0,%1,%2,%3}, [%4];"
        : "=r"(r0), "=r"(r1), "=r"(r2), "=r"(r3) : "r"(addr));
}
__device__ __forceinline__ void mma16816(float& d0, float& d1, float& d2, float& d3,
                                         uint32_t a0, uint32_t a1, uint32_t a2, uint32_t a3,
                                         uint32_t b0, uint32_t b1) {
    asm volatile("mma.sync.aligned.m16n8k16.row.col.f32.f16.f16.f32 "
        "{%0,%1,%2,%3}, {%4,%5,%6,%7}, {%8,%9}, {%0,%1,%2,%3};"
        : "+f"(d0), "+f"(d1), "+f"(d2), "+f"(d3)
        : "r"(a0), "r"(a1), "r"(a2), "r"(a3), "r"(b0), "r"(b1));
}

// ---- permutation derivation ----
__device__ int g_pos[1024];
__device__ __forceinline__ unsigned long long lanemax_ull(unsigned long long k) {
    #pragma unroll
    for (int o = 16; o; o >>= 1) {
        unsigned long long v = __shfl_xor_sync(0xffffffffu, k, o);
        if (v > k) k = v;
    }
    return k;
}
__global__ void perm_kernel(const float* __restrict__ ker) {
    __shared__ float ctab[32][33];
    int tid = threadIdx.x;
    for (int i = tid; i < 1024; i += 256) {
        int f = i >> 5, x = i & 31;
        ctab[f][x] = cospif((float)((2 * x + 1) * f) * (1.0f / 64.0f));
    }
    __syncthreads();
    int k = blockIdx.x * 8 + (tid >> 5);
    int f = tid & 31;
    const float* K = ker + (size_t)k * 1024;
    float s = 0.f, t = 0.f;
    #pragma unroll
    for (int x = 0; x < 32; x++) { float c = ctab[f][x]; s = fmaf(K[x], c, s); t = fmaf(K[x * 32], c, t); }
    unsigned long long ks = (((unsigned long long)__float_as_uint(fabsf(s))) << 32) | (unsigned)f;
    unsigned long long kt = (((unsigned long long)__float_as_uint(fabsf(t))) << 32) | (unsigned)f;
    ks = lanemax_ull(ks); kt = lanemax_ull(kt);
    if (f == 0) g_pos[(int)(kt & 31u) * 32 + (int)(ks & 31u)] = k;
}

// ---- main kernel ----
// Strip: 32 rows x 256 cols (8 blocks), grid (2,16,32), 256 threads.
// A (fp16): row rho=(c*32+v)*8+nblk, 40-half (80B) stride, 32 data halfs. 61440 B.
// S (fp32): [m'=3v+c][u_local 8][n 8], stride 72 floats. 27648 B.  pos16: 2048 B.
static constexpr int A_BYTES = 768 * 80;          // 61440
static constexpr int S_OFF   = A_BYTES;
static constexpr int S_BYTES = 96 * 72 * 4;       // 27648
static constexpr int P_OFF   = S_OFF + S_BYTES;   // 89088
static constexpr int SM_TOTAL = P_OFF + 2048;     // 91136

__global__ void __launch_bounds__(256, 2)
dct_main(const float* __restrict__ rgb, float* __restrict__ out) {
    extern __shared__ char smem[];
    __half* A = reinterpret_cast<__half*>(smem);
    float* S = reinterpret_cast<float*>(smem + S_OFF);
    unsigned short* pos_s = reinterpret_cast<unsigned short*>(smem + P_OFF);
    const uint32_t sb = smem_u32(smem);
    const int tid = threadIdx.x, wid = tid >> 5, lid = tid & 31;
    const int ng = blockIdx.x, brow = blockIdx.y, b = blockIdx.z;

    #pragma unroll
    for (int i = 0; i < 4; i++) pos_s[i * 256 + tid] = (unsigned short)g_pos[i * 256 + tid];

    // ---- stage 1: vertical DCT per RGB plane (raw), write A rows ----
    {
        const size_t plane = (size_t)512 * 512;
        const float* q0 = rgb + (size_t)b * 3 * plane + (size_t)(brow * 32) * 512 + ng * 256 + tid;
        const int g = tid >> 5, xl = tid & 31;
        #pragma unroll 1
        for (int c = 0; c < 3; c++) {
            float acc[32];
            vdct32(q0 + (size_t)c * plane, acc);
            #pragma unroll
            for (int v = 0; v < 32; v++)
                A[((c * 32 + v) * 8 + g) * 40 + xl] = __float2half_rn(acc[v]);
        }
    }
    __syncthreads();

    // ---- mix pass: raw RGB rows -> (2Y, Cb', Cr') in place (half2) ----
    {
        __half2* A2 = reinterpret_cast<__half2*>(A);
        #pragma unroll 1
        for (int i = tid; i < 5120; i += 256) {
            float2 r2 = __half22float2(A2[i]);
            float2 g2 = __half22float2(A2[i + 5120]);
            float2 b2 = __half22float2(A2[i + 10240]);
            float yx = fmaf(0.299f, r2.x, fmaf(0.587f, g2.x, 0.114f * b2.x));
            float yy = fmaf(0.299f, r2.y, fmaf(0.587f, g2.y, 0.114f * b2.y));
            A2[i]         = __floats2half2_rn(2.0f * yx, 2.0f * yy);
            A2[i + 5120]  = __floats2half2_rn((b2.x - yx) * 1.128f, (b2.y - yy) * 1.128f);
            A2[i + 10240] = __floats2half2_rn((r2.x - yx) * 1.426f, (r2.y - yy) * 1.426f);
        }
    }
    __syncthreads();

    // ---- load A fragments: warp = block n; 8 m-slices x 2 k-tiles ----
    const int n = wid;
    uint32_t fa[8][2][4];
    {
        const int rowi = lid & 15, colo = (lid >> 4) * 16;
        #pragma unroll
        for (int s = 0; s < 8; s++) {
            int m = s * 16 + rowi;
            int c = m & 3; if (c == 3) c = 0;
            int v = m >> 2;
            uint32_t base = sb + (uint32_t)(((c * 32 + v) * 8 + n) * 80) + colo;
            ldmatrix_x4(fa[s][0][0], fa[s][0][1], fa[s][0][2], fa[s][0][3], base);
            ldmatrix_x4(fa[s][1][0], fa[s][1][1], fa[s][1][2], fa[s][1][3], base + 32);
        }
    }

    const float scl = 1.0f / 16.0f;
    #pragma unroll 1
    for (int uq = 0; uq < 4; uq++) {
        // B fragments (computed, no smem): u = uq*8 + (lid>>2), k rows 2(lid&3)..
        uint32_t fb[2][2];
        {
            int u = uq * 8 + (lid >> 2);
            float f = ((u == 0) ? 0.70710678118654752f : 1.0f) * scl;
            int k0 = 2 * (lid & 3);
            #pragma unroll
            for (int kt = 0; kt < 2; kt++) {
                int kb = kt * 16 + k0;
                float h0 = cospif((float)((2 * kb + 1) * u) * (1.0f / 64.0f)) * f;
                float h1 = cospif((float)((2 * kb + 3) * u) * (1.0f / 64.0f)) * f;
                float h2 = cospif((float)((2 * (kb + 8) + 1) * u) * (1.0f / 64.0f)) * f;
                float h3 = cospif((float)((2 * (kb + 8) + 3) * u) * (1.0f / 64.0f)) * f;
                __half2 p0 = __floats2half2_rn(h0, h1), p1 = __floats2half2_rn(h2, h3);
                fb[kt][0] = *reinterpret_cast<uint32_t*>(&p0);
                fb[kt][1] = *reinterpret_cast<uint32_t*>(&p1);
            }
        }
        // mma + scatter to S
        const int r = lid >> 2, ul = 2 * (lid & 3);
        #pragma unroll
        for (int s = 0; s < 8; s++) {
            float d0 = 0.f, d1 = 0.f, d2 = 0.f, d3 = 0.f;
            mma16816(d0, d1, d2, d3, fa[s][0][0], fa[s][0][1], fa[s][0][2], fa[s][0][3], fb[0][0], fb[0][1]);
            mma16816(d0, d1, d2, d3, fa[s][1][0], fa[s][1][1], fa[s][1][2], fa[s][1][3], fb[1][0], fb[1][1]);
            int m = s * 16 + r, c = m & 3;
            if (c != 3) {
                int mp1 = (m >> 2) * 3 + c, mp2 = ((m + 8) >> 2) * 3 + c;
                S[mp1 * 72 + ul * 8 + n] = d0;
                S[mp1 * 72 + (ul + 1) * 8 + n] = d1;
                S[mp2 * 72 + ul * 8 + n] = d2;
                S[mp2 * 72 + (ul + 1) * 8 + n] = d3;
            }
        }
        __syncthreads();

        // repack: thread = (v, j); u = uq*8+j; 8 consecutive n -> 2x STG.128
        {
            const int v = tid >> 3, j = tid & 7;
            const int u = uq * 8 + j;
            const int kidx = pos_s[v * 32 + u];
            #pragma unroll
            for (int c = 0; c < 3; c++) {
                const float4* sp = reinterpret_cast<const float4*>(S + (v * 3 + c) * 72 + j * 8);
                float4 lo = sp[0], hi = sp[1];
                if (uq == 0 && v == 0 && j == 0 && c == 0) {
                    lo.x -= 32.f; lo.y -= 32.f; lo.z -= 32.f; lo.w -= 32.f;
                    hi.x -= 32.f; hi.y -= 32.f; hi.z -= 32.f; hi.w -= 32.f;
                }
                float4* op = reinterpret_cast<float4*>(
                    out + ((size_t)b * 3072 + c * 1024 + kidx) * 256 + brow * 16 + ng * 8);
                op[0] = lo; op[1] = hi;
            }
        }
        __syncthreads();
    }
}

extern "C" void kernel_launch(void* const* d_in, const int* in_sizes, int n_in,
                              void* d_out, int out_size) {
    const float* rgb = (const float*)d_in[0];
    const float* ker = (const float*)d_in[1];
    float* out = (float*)d_out;

    perm_kernel<<<128, 256>>>(ker);

    cudaFuncSetAttribute(dct_main, cudaFuncAttributeMaxDynamicSharedMemorySize, SM_TOTAL);
    dct_main<<<dim3(2, 16, 32), 256, SM_TOTAL>>>(rgb, out);
}

// round 15
// speedup vs baseline: 2.1092x; 2.1092x over previous
#include <cuda_runtime.h>
#include <cuda_fp16.h>
#include <cstdint>
#include <cstddef>

#define DH __host__ __device__

DH constexpr double tcos_core(double x) {
    double x2 = x * x, t = 1.0, s = 1.0;
    for (int i = 1; i <= 12; i++) { t *= -x2 / (double)((2 * i - 1) * (2 * i)); s += t; }
    return s;
}
// cos((2p+1) * f * pi / (2N)) with exact integer reduction.
DH constexpr double dcosg(int f, int p, int N) {
    int m = ((2 * p + 1) * f) % (4 * N);
    double sg = 1.0;
    if (m > 2 * N) m = 4 * N - m;
    if (m > N) { sg = -1.0; m = 2 * N - m; }
    const double PI = 3.14159265358979323846264338327950288;
    return sg * tcos_core((double)m * PI / (2.0 * N));
}
DH constexpr double rsqrt2c() {
    double g = 0.7;
    for (int i = 0; i < 50; i++) g = 0.5 * (g + 0.5 / g);
    return g;
}
// Stage factor: S=0 vertical (fold c_v), S=1 horizontal (fold c_u and 2/32).
DH constexpr double facs(int S, int v) {
    double f = (v == 0) ? rsqrt2c() : 1.0;
    return S ? f * (1.0 / 16.0) : f;
}
// Level-3 split of the 32-point DCT-II:
//  v=2w+1   from d[16]   (16x16)
//  v=4t+2   from sd[8]   (8x8)
//  v=8r     from sss[4]  (4x4, DCT-4)
//  v=8r+4   from ssd[4]  (4x4)
DH constexpr float codd(int S, int w, int p) { return (float)(dcosg(2 * w + 1, p, 32) * facs(S, 2 * w + 1)); }
DH constexpr float ceo8(int S, int t, int q) { return (float)(dcosg(2 * t + 1, q, 16) * facs(S, 4 * t + 2)); }
DH constexpr float ce4e(int S, int r, int q) { return (float)(dcosg(r,         q,  4) * facs(S, 8 * r)); }
DH constexpr float ce4o(int S, int r, int q) { return (float)(dcosg(2 * r + 1, q,  8) * facs(S, 8 * r + 4)); }

// ---- odd part: d[16] -> ao[16] ----
template <int S, int P, int W> struct OddW {
    static __device__ __forceinline__ void run(float dv, float (&a)[16]) {
        a[W] = fmaf(dv, codd(S, W, P), a[W]); OddW<S, P, W + 1>::run(dv, a);
    }
};
template <int S, int P> struct OddW<S, P, 16> { static __device__ __forceinline__ void run(float, float (&)[16]) {} };
template <int S, int P> struct OddIn {
    static __device__ __forceinline__ void run(const float (&d)[16], float (&a)[16]) {
        OddW<S, P, 0>::run(d[P], a); OddIn<S, P + 1>::run(d, a);
    }
};
template <int S> struct OddIn<S, 16> { static __device__ __forceinline__ void run(const float (&)[16], float (&)[16]) {} };

// ---- even-odd part: sd[8] -> ao2[8] ----
template <int S, int Q, int T> struct Eo8W {
    static __device__ __forceinline__ void run(float v, float (&a)[8]) {
        a[T] = fmaf(v, ceo8(S, T, Q), a[T]); Eo8W<S, Q, T + 1>::run(v, a);
    }
};
template <int S, int Q> struct Eo8W<S, Q, 8> { static __device__ __forceinline__ void run(float, float (&)[8]) {} };
template <int S, int Q> struct Eo8In {
    static __device__ __forceinline__ void run(const float (&sd)[8], float (&a)[8]) {
        Eo8W<S, Q, 0>::run(sd[Q], a); Eo8In<S, Q + 1>::run(sd, a);
    }
};
template <int S> struct Eo8In<S, 8> { static __device__ __forceinline__ void run(const float (&)[8], float (&)[8]) {} };

// ---- level-3: sss[4] -> aee[4] (v=8r), ssd[4] -> aoo[4] (v=8r+4) ----
template <int S, int Q, int R> struct E4W {
    static __device__ __forceinline__ void run(float se, float so, float (&aee)[4], float (&aoo)[4]) {
        aee[R] = fmaf(se, ce4e(S, R, Q), aee[R]);
        aoo[R] = fmaf(so, ce4o(S, R, Q), aoo[R]);
        E4W<S, Q, R + 1>::run(se, so, aee, aoo);
    }
};
template <int S, int Q> struct E4W<S, Q, 4> { static __device__ __forceinline__ void run(float, float, float (&)[4], float (&)[4]) {} };
template <int S, int Q> struct E4In {
    static __device__ __forceinline__ void run(const float (&sss)[4], const float (&ssd)[4],
                                               float (&aee)[4], float (&aoo)[4]) {
        E4W<S, Q, 0>::run(sss[Q], ssd[Q], aee, aoo); E4In<S, Q + 1>::run(sss, ssd, aee, aoo);
    }
};
template <int S> struct E4In<S, 4> { static __device__ __forceinline__ void run(const float (&)[4], const float (&)[4], float (&)[4], float (&)[4]) {} };

// Full 32-point DCT-II core from s/d arrays -> out[32] (v-indexed).
template <int S>
__device__ __forceinline__ void dct32_core(const float (&s)[16], const float (&d)[16], float (&out)[32]) {
    float ao[16];
    #pragma unroll
    for (int w = 0; w < 16; w++) ao[w] = 0.f;
    OddIn<S, 0>::run(d, ao);

    float ss[8], sd[8];
    #pragma unroll
    for (int q = 0; q < 8; q++) { ss[q] = s[q] + s[15 - q]; sd[q] = s[q] - s[15 - q]; }
    float ao2[8];
    #pragma unroll
    for (int t = 0; t < 8; t++) ao2[t] = 0.f;
    Eo8In<S, 0>::run(sd, ao2);

    float sss[4], ssd[4];
    #pragma unroll
    for (int q = 0; q < 4; q++) { sss[q] = ss[q] + ss[7 - q]; ssd[q] = ss[q] - ss[7 - q]; }
    float aee[4], aoo[4];
    #pragma unroll
    for (int r = 0; r < 4; r++) { aee[r] = 0.f; aoo[r] = 0.f; }
    E4In<S, 0>::run(sss, ssd, aee, aoo);

    #pragma unroll
    for (int w = 0; w < 16; w++) out[2 * w + 1] = ao[w];
    #pragma unroll
    for (int t = 0; t < 8; t++) out[4 * t + 2] = ao2[t];
    #pragma unroll
    for (int r = 0; r < 4; r++) { out[8 * r] = aee[r]; out[8 * r + 4] = aoo[r]; }
}

// ---- permutation derivation from the kernels input ----
__device__ int g_pos[1024];  // pos[v*32+u] = output channel index k

__device__ __forceinline__ unsigned long long lanemax_ull(unsigned long long k) {
    #pragma unroll
    for (int o = 16; o; o >>= 1) {
        unsigned long long v = __shfl_xor_sync(0xffffffffu, k, o);
        if (v > k) k = v;
    }
    return k;
}

__global__ void perm_kernel(const float* __restrict__ ker) {
    __shared__ float ctab[32][33];
    int tid = threadIdx.x;
    for (int i = tid; i < 1024; i += 256) {
        int f = i >> 5, x = i & 31;
        ctab[f][x] = cospif((float)((2 * x + 1) * f) * (1.0f / 64.0f));
    }
    __syncthreads();
    int k = blockIdx.x * 8 + (tid >> 5);
    int f = tid & 31;
    const float* K = ker + (size_t)k * 1024;
    float s = 0.f, t = 0.f;
    #pragma unroll
    for (int x = 0; x < 32; x++) { float c = ctab[f][x]; s = fmaf(K[x], c, s); t = fmaf(K[x * 32], c, t); }
    unsigned long long ks = (((unsigned long long)__float_as_uint(fabsf(s))) << 32) | (unsigned)f;
    unsigned long long kt = (((unsigned long long)__float_as_uint(fabsf(t))) << 32) | (unsigned)f;
    ks = lanemax_ull(ks); kt = lanemax_ull(kt);
    if (f == 0) g_pos[(int)(kt & 31u) * 32 + (int)(ks & 31u)] = k;
}

// ---- main fused kernel ----
// Grid: (ng=2, m=16, b=32). CTA = 256 threads, one 32-row x 256-col strip (8 blocks).
// tmp (fp16) planes: [c][v][x] at c*8704 + v*272 + (x/32)*34 + (x%32) halfs.
// pos_s: u16[32][36] padded rows -> pair loads are 4B-aligned and conflict-free.
static constexpr int ROW_HALFS = 272;
static constexpr int PLANE_HALFS = 32 * ROW_HALFS;    // 8704
static constexpr int TMP_HALFS = 3 * PLANE_HALFS;     // 26112 halfs = 52224 B
static constexpr int PLANE_H2 = PLANE_HALFS / 2;      // 4352

__global__ void __launch_bounds__(256, 4)
dct_main(const float* __restrict__ rgb, float* __restrict__ out) {
    extern __shared__ __half tmp[];
    __shared__ unsigned short pos_s[32 * 36];

    const int tid = threadIdx.x;
    const int ng = blockIdx.x;
    const int m  = blockIdx.y;
    const int b  = blockIdx.z;

    #pragma unroll
    for (int i = 0; i < 4; i++) {
        int idx = i * 256 + tid;
        pos_s[(idx >> 5) * 36 + (idx & 31)] = (unsigned short)g_pos[idx];
    }

    // ---- stage 1: per-plane vertical level-3 butterfly DCT. thread = col, loop c. ----
    {
        const size_t plane = (size_t)512 * 512;
        const float* q0 = rgb + (size_t)b * 3 * plane + (size_t)(m * 32) * 512 + ng * 256 + tid;
        const int go = (tid >> 5) * 34 + (tid & 31);

        #pragma unroll 1
        for (int c = 0; c < 3; c++) {
            const float* q = q0 + (size_t)c * plane;
            float s[16], d[16];
            #pragma unroll
            for (int P = 0; P < 16; P++) {
                float lo = __ldcs(q + P * 512), hi = __ldcs(q + (31 - P) * 512);
                s[P] = lo + hi; d[P] = lo - hi;
            }
            float o32[32];
            dct32_core<0>(s, d, o32);
            __half* tb = tmp + c * PLANE_HALFS + go;
            #pragma unroll
            for (int v = 0; v < 32; v++)
                tb[v * ROW_HALFS] = __float2half_rn(o32[v]);
        }
    }
    __syncthreads();

    // ---- mix pass (half2-vectorized): RGB planes -> (2Y, Cb', Cr') in place ----
    {
        __half2* t2 = reinterpret_cast<__half2*>(tmp);
        #pragma unroll 1
        for (int i = tid; i < PLANE_H2; i += 256) {
            float2 r2 = __half22float2(t2[i]);
            float2 g2 = __half22float2(t2[PLANE_H2 + i]);
            float2 b2 = __half22float2(t2[2 * PLANE_H2 + i]);
            float y0x = fmaf(0.299f, r2.x, fmaf(0.587f, g2.x, 0.114f * b2.x));
            float y0y = fmaf(0.299f, r2.y, fmaf(0.587f, g2.y, 0.114f * b2.y));
            t2[i]                = __floats2half2_rn(2.0f * y0x, 2.0f * y0y);
            t2[PLANE_H2 + i]     = __floats2half2_rn((b2.x - y0x) * 1.128f, (b2.y - y0y) * 1.128f);
            t2[2 * PLANE_H2 + i] = __floats2half2_rn((r2.x - y0x) * 1.426f, (r2.y - y0y) * 1.426f);
        }
    }
    __syncthreads();

    // ---- stage 2: horizontal level-3 butterfly DCT. thread = (v, nblk), loop c. ----
    {
        const int v = tid >> 3, nblk = tid & 7;
        const int n = ng * 8 + nblk;
        float* ob = out + (((size_t)b * 3072) * 16 + m) * 16 + n;
        const uint32_t* pprow = reinterpret_cast<const uint32_t*>(pos_s + v * 36);

        #pragma unroll 1
        for (int c = 0; c < 3; c++) {
            const __half2* t2 = reinterpret_cast<const __half2*>(
                tmp + c * PLANE_HALFS + v * ROW_HALFS + nblk * 34);

            float vals[32];
            #pragma unroll
            for (int j = 0; j < 16; j++) {
                float2 f2 = __half22float2(t2[j]);
                vals[2 * j] = f2.x; vals[2 * j + 1] = f2.y;
            }
            float s[16], d[16];
            #pragma unroll
            for (int P = 0; P < 16; P++) {
                s[P] = vals[P] + vals[31 - P];
                d[P] = vals[P] - vals[31 - P];
            }

            float a2[32];
            dct32_core<1>(s, d, a2);

            if (c == 0 && v == 0) a2[0] -= 32.0f;   // DC term of the "-1" offset

            float* obc = ob + (size_t)c * 1024 * 256;
            #pragma unroll
            for (int j = 0; j < 16; j++) {
                uint32_t pk = pprow[j];
                __stcs(obc + (size_t)(pk & 0xFFFFu) * 256, a2[2 * j]);
                __stcs(obc + (size_t)(pk >> 16) * 256,     a2[2 * j + 1]);
            }
        }
    }
}

// ---------------- launch ----------------
extern "C" void kernel_launch(void* const* d_in, const int* in_sizes, int n_in,
                              void* d_out, int out_size) {
    const float* rgb = (const float*)d_in[0];
    const float* ker = (const float*)d_in[1];
    float* out = (float*)d_out;

    perm_kernel<<<128, 256>>>(ker);

    cudaFuncSetAttribute(dct_main, cudaFuncAttributeMaxDynamicSharedMemorySize,
                         TMP_HALFS * (int)sizeof(__half));
    dct_main<<<dim3(2, 16, 32), 256, TMP_HALFS * (int)sizeof(__half)>>>(rgb, out);
}